// round 6
// baseline (speedup 1.0000x reference)
#include <cuda_runtime.h>
#include <cuda_bf16.h>
#include <cstdint>

// Problem constants
#define N_ROWS 16384
#define M_ROWS 1024
#define D_DIM  256
#define OUT_EPS 1e-6f

// GEMM tiling (tf32)
#define BM 128
#define BN 128
#define BK 16
#define KPAD 4
#define KSTRIDE (BK + KPAD)   // 20 floats = 80B row stride (16B aligned)

// Scratch (allocation-free rule: __device__ globals). tf32-rounded fp32.
__device__ float g_xb[N_ROWS * D_DIM];
__device__ float g_pb[M_ROWS * D_DIM];
__device__ float g_xn[N_ROWS];
__device__ float g_pn[M_ROWS];

__device__ __forceinline__ float to_tf32(float v)
{
    float r;
    asm("cvt.rna.tf32.f32 %0, %1;" : "=f"(r) : "f"(v));
    return r;
}

// ---------------------------------------------------------------------------
// Prep (fused x+p): wv = v*fw ; store tf32-rounded fp32 ; norm = sum(wv^2) fp32.
// One warp per row; lane handles 8 consecutive floats (2x float4).
// ---------------------------------------------------------------------------
__global__ void prep_kernel(const float* __restrict__ x,
                            const float* __restrict__ p,
                            const float* __restrict__ fw)
{
    int gw   = (blockIdx.x * blockDim.x + threadIdx.x) >> 5;
    int lane = threadIdx.x & 31;
    if (gw >= N_ROWS + M_ROWS) return;

    const float* src;
    float* dst;
    float* norms;
    int row;
    if (gw < N_ROWS) { row = gw;          src = x; dst = g_xb; norms = g_xn; }
    else             { row = gw - N_ROWS; src = p; dst = g_pb; norms = g_pn; }

    const float4* r4 = reinterpret_cast<const float4*>(src + (size_t)row * D_DIM) + lane * 2;
    const float4* w4 = reinterpret_cast<const float4*>(fw) + lane * 2;
    float4* o4       = reinterpret_cast<float4*>(dst + (size_t)row * D_DIM) + lane * 2;

    float4 a0 = r4[0], a1 = r4[1];
    float4 w0 = w4[0], w1 = w4[1];

    float v0 = a0.x * w0.x, v1 = a0.y * w0.y, v2 = a0.z * w0.z, v3 = a0.w * w0.w;
    float v4 = a1.x * w1.x, v5 = a1.y * w1.y, v6 = a1.z * w1.z, v7 = a1.w * w1.w;

    float s = 0.f;
    s = fmaf(v0, v0, s); s = fmaf(v1, v1, s); s = fmaf(v2, v2, s); s = fmaf(v3, v3, s);
    s = fmaf(v4, v4, s); s = fmaf(v5, v5, s); s = fmaf(v6, v6, s); s = fmaf(v7, v7, s);

    o4[0] = make_float4(to_tf32(v0), to_tf32(v1), to_tf32(v2), to_tf32(v3));
    o4[1] = make_float4(to_tf32(v4), to_tf32(v5), to_tf32(v6), to_tf32(v7));

#pragma unroll
    for (int off = 16; off; off >>= 1)
        s += __shfl_xor_sync(0xffffffffu, s, off);
    if (lane == 0) norms[row] = s;
}

// ---------------------------------------------------------------------------
// asm helpers
// ---------------------------------------------------------------------------
__device__ __forceinline__ void cp_async_16(void* smem_dst, const void* gmem_src)
{
    uint32_t daddr = (uint32_t)__cvta_generic_to_shared(smem_dst);
    asm volatile("cp.async.cg.shared.global [%0], [%1], 16;"
                 :: "r"(daddr), "l"(gmem_src) : "memory");
}

__device__ __forceinline__ void cp_async_commit()
{
    asm volatile("cp.async.commit_group;" ::: "memory");
}

template <int NWait>
__device__ __forceinline__ void cp_async_wait()
{
    asm volatile("cp.async.wait_group %0;" :: "n"(NWait) : "memory");
}

__device__ __forceinline__ void mma_tf32(float* c, const uint32_t* a, const uint32_t* b)
{
    asm volatile(
        "mma.sync.aligned.m16n8k8.row.col.f32.tf32.tf32.f32 "
        "{%0,%1,%2,%3}, {%4,%5,%6,%7}, {%8,%9}, {%0,%1,%2,%3};"
        : "+f"(c[0]), "+f"(c[1]), "+f"(c[2]), "+f"(c[3])
        : "r"(a[0]), "r"(a[1]), "r"(a[2]), "r"(a[3]),
          "r"(b[0]), "r"(b[1]));
}

// B-row permutation within each 32-row group:
// smem slot s = 8j+g holds prototype 8*(g>>1) + 2j + (g&1), so that thread
// (g,t) ends up owning 8 CONTIGUOUS output columns [8t, 8t+8) after 4 nt tiles.
// Inverse (store side): proto p -> slot ((p>>1)&3)<<3 | ((p>>3)&3)<<1 | (p&1).
__device__ __forceinline__ int perm_b_row(int r)
{
    int p5 = r & 31;
    int s5 = (((p5 >> 1) & 3) << 3) | (((p5 >> 3) & 3) << 1) | (p5 & 1);
    return (r & ~31) | s5;
}

// ---------------------------------------------------------------------------
// Fused GEMM + epilogue.
// dot[i,j] = wx[i,:] . wp[j,:]   (tf32 mma.sync m16n8k8, fp32 accum)
// sq = xn[i] + pn[j] - 2*dot ; d = sqrt(max(sq,0)+eps) ; s = exp(-T*d)
// out[0 .. N*M) = similarities ; out[N*M .. 2*N*M) = distances
// ---------------------------------------------------------------------------
__global__ __launch_bounds__(256, 2)
void gemm_kernel(const float* __restrict__ tptr, float* __restrict__ out)
{
    __shared__ float sA[2][BM][KSTRIDE];
    __shared__ float sB[2][BN][KSTRIDE];

    const int tid  = threadIdx.x;
    const int warp = tid >> 5;
    const int lane = tid & 31;
    const int bm   = blockIdx.y;   // N tile
    const int bn   = blockIdx.x;   // M tile

    const int wm = (warp >> 2) * 64;  // warp row offset within 128 (2 warps)
    const int wn = (warp & 3) * 32;   // warp col offset within 128 (4 warps)

    const int g = lane >> 2;          // groupID   (0..7)
    const int t = lane & 3;           // tid-in-group (0..3)

    float acc[4][4][4];
#pragma unroll
    for (int i = 0; i < 4; ++i)
#pragma unroll
        for (int j = 0; j < 4; ++j)
#pragma unroll
            for (int k = 0; k < 4; ++k) acc[i][j][k] = 0.f;

    const float* gA = g_xb + (size_t)bm * BM * D_DIM;
    const float* gB = g_pb + (size_t)bn * BN * D_DIM;

    // Stage loader: per tile 128 rows x 16 floats = 512 x 16B chunks;
    // 256 threads -> 2 chunks each (A and B). B rows stored PERMUTED.
    const int row0  = tid >> 2;              // 0..63
    const int c0    = (tid & 3) * 4;         // float index 0,4,8,12
    const int row1  = row0 + 64;             // 64..127
    const int brow0 = perm_b_row(row0);
    const int brow1 = perm_b_row(row1);

    const int NK = D_DIM / BK;  // 16

#pragma unroll 1
    for (int kt = -1; kt < NK; ++kt) {
        int ktn = kt + 1;
        if (ktn < NK) {
            int buf = ktn & 1;
            int k0  = ktn * BK;
            cp_async_16(&sA[buf][row0][c0],  gA + (size_t)row0 * D_DIM + k0 + c0);
            cp_async_16(&sB[buf][brow0][c0], gB + (size_t)row0 * D_DIM + k0 + c0);
            cp_async_16(&sA[buf][row1][c0],  gA + (size_t)row1 * D_DIM + k0 + c0);
            cp_async_16(&sB[buf][brow1][c0], gB + (size_t)row1 * D_DIM + k0 + c0);
            cp_async_commit();
        }
        if (kt < 0) { cp_async_wait<0>(); __syncthreads(); continue; }
        if (ktn < NK) cp_async_wait<1>(); else cp_async_wait<0>();

        const int buf = kt & 1;
#pragma unroll
        for (int ks = 0; ks < BK / 8; ++ks) {
            const int k0 = ks * 8;
            uint32_t af[4][4];
            uint32_t bf[4][2];
#pragma unroll
            for (int mt = 0; mt < 4; ++mt) {
                const int r = wm + mt * 16;
                af[mt][0] = __float_as_uint(sA[buf][r + g    ][k0 + t    ]);
                af[mt][1] = __float_as_uint(sA[buf][r + g + 8][k0 + t    ]);
                af[mt][2] = __float_as_uint(sA[buf][r + g    ][k0 + t + 4]);
                af[mt][3] = __float_as_uint(sA[buf][r + g + 8][k0 + t + 4]);
            }
#pragma unroll
            for (int nt = 0; nt < 4; ++nt) {
                const int c = wn + nt * 8;   // permuted slots, conflict-free loads
                bf[nt][0] = __float_as_uint(sB[buf][c + g][k0 + t    ]);
                bf[nt][1] = __float_as_uint(sB[buf][c + g][k0 + t + 4]);
            }
#pragma unroll
            for (int mt = 0; mt < 4; ++mt)
#pragma unroll
                for (int nt = 0; nt < 4; ++nt)
                    mma_tf32(acc[mt][nt], af[mt], bf[nt]);
        }
        __syncthreads();
    }

    // ----- fused epilogue -----
    // With the B permutation, tile nt's pair for thread t sits at actual
    // columns 8t + 2*nt (+1): thread owns 8 contiguous columns -> float4 x2.
    const float temp = *tptr;
    const int grow0 = bm * BM + wm + g;
    const int gcolb = bn * BN + wn + 8 * t;  // 32B-aligned base column

    float* simo  = out;
    float* disto = out + (size_t)N_ROWS * M_ROWS;

#pragma unroll
    for (int mt = 0; mt < 4; ++mt) {
        const int r0 = grow0 + mt * 16;
        const float xn0 = g_xn[r0];
        const float xn1 = g_xn[r0 + 8];

        float d0[8], d1[8], s0[8], s1[8];
#pragma unroll
        for (int nt = 0; nt < 4; ++nt) {
            const float pn0 = g_pn[gcolb + 2 * nt];
            const float pn1 = g_pn[gcolb + 2 * nt + 1];

            float sq00 = xn0 + pn0 - 2.f * acc[mt][nt][0];
            float sq01 = xn0 + pn1 - 2.f * acc[mt][nt][1];
            float sq10 = xn1 + pn0 - 2.f * acc[mt][nt][2];
            float sq11 = xn1 + pn1 - 2.f * acc[mt][nt][3];

            d0[2*nt]   = sqrtf(fmaxf(sq00, 0.f) + OUT_EPS);
            d0[2*nt+1] = sqrtf(fmaxf(sq01, 0.f) + OUT_EPS);
            d1[2*nt]   = sqrtf(fmaxf(sq10, 0.f) + OUT_EPS);
            d1[2*nt+1] = sqrtf(fmaxf(sq11, 0.f) + OUT_EPS);

            s0[2*nt]   = __expf(-temp * d0[2*nt]);
            s0[2*nt+1] = __expf(-temp * d0[2*nt+1]);
            s1[2*nt]   = __expf(-temp * d1[2*nt]);
            s1[2*nt+1] = __expf(-temp * d1[2*nt+1]);
        }

        size_t i0 = (size_t)r0 * M_ROWS + gcolb;
        size_t i1 = (size_t)(r0 + 8) * M_ROWS + gcolb;

        __stcs(reinterpret_cast<float4*>(simo + i0),
               make_float4(s0[0], s0[1], s0[2], s0[3]));
        __stcs(reinterpret_cast<float4*>(simo + i0 + 4),
               make_float4(s0[4], s0[5], s0[6], s0[7]));
        __stcs(reinterpret_cast<float4*>(simo + i1),
               make_float4(s1[0], s1[1], s1[2], s1[3]));
        __stcs(reinterpret_cast<float4*>(simo + i1 + 4),
               make_float4(s1[4], s1[5], s1[6], s1[7]));

        __stcs(reinterpret_cast<float4*>(disto + i0),
               make_float4(d0[0], d0[1], d0[2], d0[3]));
        __stcs(reinterpret_cast<float4*>(disto + i0 + 4),
               make_float4(d0[4], d0[5], d0[6], d0[7]));
        __stcs(reinterpret_cast<float4*>(disto + i1),
               make_float4(d1[0], d1[1], d1[2], d1[3]));
        __stcs(reinterpret_cast<float4*>(disto + i1 + 4),
               make_float4(d1[4], d1[5], d1[6], d1[7]));
    }
}

// ---------------------------------------------------------------------------
extern "C" void kernel_launch(void* const* d_in, const int* in_sizes, int n_in,
                              void* d_out, int out_size)
{
    (void)in_sizes; (void)n_in; (void)out_size;
    const float* x  = (const float*)d_in[0];
    const float* p  = (const float*)d_in[1];
    const float* fw = (const float*)d_in[2];
    const float* t  = (const float*)d_in[3];
    float* out = (float*)d_out;

    // fused prep: (16384 + 1024) rows, 1 warp/row, 8 warps/block
    prep_kernel<<<(N_ROWS + M_ROWS) / 8, 256>>>(x, p, fw);

    dim3 grid(M_ROWS / BN, N_ROWS / BM);  // (8, 128)
    gemm_kernel<<<grid, 256>>>(t, out);
}